// round 10
// baseline (speedup 1.0000x reference)
#include <cuda_runtime.h>
#include <cuda_bf16.h>
#include <cstdint>
#include <cstddef>

// ---------------------------------------------------------------------------
// Problem constants
// ---------------------------------------------------------------------------
#define BB   2
#define LL   2048
#define DD   512
#define HH   8
#define DHH  64
#define DFCN 2048
#define MM   (BB * LL)        // 4096 rows

typedef unsigned long long u64;
typedef unsigned int u32;

// ---------------------------------------------------------------------------
// Scratch (device globals: allocation-guard-safe)
// ---------------------------------------------------------------------------
__device__ __nv_bfloat16 g_xh[MM * DD],   g_xl[MM * DD];      // split x
__device__ __nv_bfloat16 g_qh[MM * DD],   g_ql[MM * DD];      // split scaled Q
__device__ __nv_bfloat16 g_kh[MM * DD],   g_kl[MM * DD];      // split K
__device__ __nv_bfloat16 g_vth[BB*HH*DHH * LL], g_vtl[BB*HH*DHH * LL]; // V^T split
__device__ __nv_bfloat16 g_relh[LL * DD], g_rell[LL * DD];    // split rel_emb
__device__ __nv_bfloat16 g_ah[MM * DD],   g_al[MM * DD];      // split attn out
__device__ __nv_bfloat16 g_hh[MM * DFCN], g_hl[MM * DFCN];    // split FFN hidden

// Transposed + split weights: T[n][k] = W[k][n]
__device__ __nv_bfloat16 g_wqh[DD * DD],   g_wql[DD * DD];
__device__ __nv_bfloat16 g_wkh[DD * DD],   g_wkl[DD * DD];
__device__ __nv_bfloat16 g_wvh[DD * DD],   g_wvl[DD * DD];
__device__ __nv_bfloat16 g_w1h[DFCN * DD], g_w1l[DFCN * DD];
__device__ __nv_bfloat16 g_w2h[DD * DFCN], g_w2l[DD * DFCN];

// ---------------------------------------------------------------------------
// Helpers
// ---------------------------------------------------------------------------
__device__ __forceinline__ u32 smem_u32(const void* p) {
    u32 a;
    asm("{ .reg .u64 t; cvta.to.shared.u64 t, %1; cvt.u32.u64 %0, t; }"
        : "=r"(a) : "l"(p));
    return a;
}

__device__ __forceinline__ u32 pack_bf2(__nv_bfloat16 a, __nv_bfloat16 b) {
    return (u32)__bfloat16_as_ushort(a) | ((u32)__bfloat16_as_ushort(b) << 16);
}

__device__ __forceinline__ void split2(float x, float y, u32& hp, u32& lp) {
    __nv_bfloat16 hx = __float2bfloat16(x), hy = __float2bfloat16(y);
    hp = pack_bf2(hx, hy);
    lp = pack_bf2(__float2bfloat16(x - __bfloat162float(hx)),
                  __float2bfloat16(y - __bfloat162float(hy)));
}

#define LDSM_X4(r, addr) \
    asm volatile("ldmatrix.sync.aligned.m8n8.x4.shared.b16 {%0,%1,%2,%3}, [%4];" \
        : "=r"((r)[0]), "=r"((r)[1]), "=r"((r)[2]), "=r"((r)[3]) : "r"(addr))

#define MMA_BF16(d, a, b0, b1) \
    asm volatile("mma.sync.aligned.m16n8k16.row.col.f32.bf16.bf16.f32 " \
        "{%0,%1,%2,%3}, {%4,%5,%6,%7}, {%8,%9}, {%0,%1,%2,%3};" \
        : "+f"((d)[0]), "+f"((d)[1]), "+f"((d)[2]), "+f"((d)[3]) \
        : "r"((a)[0]), "r"((a)[1]), "r"((a)[2]), "r"((a)[3]), "r"(b0), "r"(b1))

__device__ __forceinline__ void cp16(u32 dst, const void* src) {
    asm volatile("cp.async.cg.shared.global [%0], [%1], 16;"
                 :: "r"(dst), "l"(src) : "memory");
}
#define CP_COMMIT()  asm volatile("cp.async.commit_group;" ::: "memory")
#define CP_WAIT(n)   asm volatile("cp.async.wait_group %0;" :: "n"(n) : "memory")

// ---------------------------------------------------------------------------
// Prep kernels
// ---------------------------------------------------------------------------
// 3 same-shape weight transposes in one launch (z selects matrix)
__global__ __launch_bounds__(256)
void tsplit3_kernel(const float* __restrict__ wq, const float* __restrict__ wk,
                    const float* __restrict__ wv,
                    __nv_bfloat16* __restrict__ qhh, __nv_bfloat16* __restrict__ qll,
                    __nv_bfloat16* __restrict__ khh, __nv_bfloat16* __restrict__ kll,
                    __nv_bfloat16* __restrict__ vhh, __nv_bfloat16* __restrict__ vll)
{
    const float* W = blockIdx.z == 0 ? wq : blockIdx.z == 1 ? wk : wv;
    __nv_bfloat16* Th = blockIdx.z == 0 ? qhh : blockIdx.z == 1 ? khh : vhh;
    __nv_bfloat16* Tl = blockIdx.z == 0 ? qll : blockIdx.z == 1 ? kll : vll;

    __shared__ float t[32][33];
    const int n0 = blockIdx.x * 32, k0 = blockIdx.y * 32;
    const int tx = threadIdx.x & 31, ty = threadIdx.x >> 5;
#pragma unroll
    for (int i = 0; i < 4; i++)
        t[ty + 8 * i][tx] = W[(size_t)(k0 + ty + 8 * i) * DD + n0 + tx];
    __syncthreads();
#pragma unroll
    for (int i = 0; i < 4; i++) {
        int n = n0 + ty + 8 * i;
        float v = t[tx][ty + 8 * i];
        __nv_bfloat16 h = __float2bfloat16(v);
        Th[(size_t)n * DD + k0 + tx] = h;
        Tl[(size_t)n * DD + k0 + tx] = __float2bfloat16(v - __bfloat162float(h));
    }
}

// w1 + w2 transpose fused: z=0 -> w1 (K=DD, N=DFCN), z=1 -> w2 (K=DFCN, N=DD),
// grid (64, 16, 2), x/y roles swapped for z=1 (perfect packing).
__global__ __launch_bounds__(256)
void tsplit_ffn_kernel(const float* __restrict__ w1, const float* __restrict__ w2,
                       __nv_bfloat16* __restrict__ w1h, __nv_bfloat16* __restrict__ w1l,
                       __nv_bfloat16* __restrict__ w2h, __nv_bfloat16* __restrict__ w2l)
{
    const int z = blockIdx.z;
    const float* W = z == 0 ? w1 : w2;
    __nv_bfloat16* Th = z == 0 ? w1h : w2h;
    __nv_bfloat16* Tl = z == 0 ? w1l : w2l;
    const int K = z == 0 ? DD : DFCN;
    const int N = z == 0 ? DFCN : DD;
    const int n0 = (z == 0 ? blockIdx.x : blockIdx.y) * 32;
    const int k0 = (z == 0 ? blockIdx.y : blockIdx.x) * 32;

    __shared__ float t[32][33];
    const int tx = threadIdx.x & 31, ty = threadIdx.x >> 5;
#pragma unroll
    for (int i = 0; i < 4; i++)
        t[ty + 8 * i][tx] = W[(size_t)(k0 + ty + 8 * i) * N + n0 + tx];
    __syncthreads();
#pragma unroll
    for (int i = 0; i < 4; i++) {
        int n = n0 + ty + 8 * i;
        float v = t[tx][ty + 8 * i];
        __nv_bfloat16 h = __float2bfloat16(v);
        Th[(size_t)n * K + k0 + tx] = h;
        Tl[(size_t)n * K + k0 + tx] = __float2bfloat16(v - __bfloat162float(h));
    }
}

// Fused elementwise split of x and rel_emb (one launch)
#define N4X (MM * DD / 4)
#define N4R (LL * DD / 4)
__global__ __launch_bounds__(256)
void conv_xrel_kernel(const float4* __restrict__ X, const float4* __restrict__ R,
                      __nv_bfloat16* __restrict__ XH, __nv_bfloat16* __restrict__ XL,
                      __nv_bfloat16* __restrict__ RH, __nv_bfloat16* __restrict__ RL)
{
    int i = blockIdx.x * blockDim.x + threadIdx.x;
    const float4* src; __nv_bfloat16 *H, *L; int j;
    if (i < N4X) { src = X; H = XH; L = XL; j = i; }
    else if (i < N4X + N4R) { src = R; H = RH; L = RL; j = i - N4X; }
    else return;
    float4 v = src[j];
    u32 h0, l0, h1, l1;
    split2(v.x, v.y, h0, l0);
    split2(v.z, v.w, h1, l1);
    *(uint2*)(H + 4 * (size_t)j) = make_uint2(h0, h1);
    *(uint2*)(L + 4 * (size_t)j) = make_uint2(l0, l1);
}

// ---------------------------------------------------------------------------
// Split-bf16 HMMA GEMM core: BK=64, 3-stage cp.async ring, 128x128 CTA tile,
// 8 warps (2x4), 64x32 warp tile. Smem rows 128B, XOR-8 swizzle.
// Pass-major MMA ordering: all hi*hi, then hi*lo, then lo*hi (RAW distance 16).
// ---------------------------------------------------------------------------
#define TGX_TILE  16384
#define TGX_STAGE (4 * TGX_TILE)
#define TGX_SMEM  (3 * TGX_STAGE)       // 192KB

__device__ __forceinline__ void load_tile64(const __nv_bfloat16* __restrict__ src,
                                            int ldk, u32 sdst, int tid)
{
#pragma unroll
    for (int i = 0; i < 4; i++) {
        int idx = tid + 256 * i;
        int r = idx >> 3, c = idx & 7;
        cp16(sdst + r * 128 + 16 * (c ^ (r & 7)), src + (size_t)r * ldk + 8 * c);
    }
}

__device__ __forceinline__ void tgx_stage_load(
    u32 sdst, const __nv_bfloat16* Ah, const __nv_bfloat16* Al,
    const __nv_bfloat16* Bh, const __nv_bfloat16* Bl, int K, int kofs, int tid)
{
    load_tile64(Ah + kofs, K, sdst,                tid);
    load_tile64(Al + kofs, K, sdst +     TGX_TILE, tid);
    load_tile64(Bh + kofs, K, sdst + 2 * TGX_TILE, tid);
    load_tile64(Bl + kofs, K, sdst + 3 * TGX_TILE, tid);
}

__device__ __forceinline__ void tgx_compute_chunk(
    u32 base, int wm, int wn, int lr16, int lc, float acc[4][4][4])
{
    const u32 sAh = base, sAl = base + TGX_TILE,
              sBh = base + 2 * TGX_TILE, sBl = base + 3 * TGX_TILE;
#pragma unroll
    for (int ks = 0; ks < 4; ks++) {
        u32 ah[4][4], al[4][4], bh[2][4], bl[2][4];
#pragma unroll
        for (int mt = 0; mt < 4; mt++) {
            int r  = wm * 64 + mt * 16 + lr16;
            int ch = 2 * ks + lc;
            u32 off = r * 128 + 16 * (ch ^ (r & 7));
            LDSM_X4(ah[mt], sAh + off);
            LDSM_X4(al[mt], sAl + off);
        }
#pragma unroll
        for (int ng = 0; ng < 2; ng++) {
            int r  = wn * 32 + ng * 16 + lr16;
            int ch = 2 * ks + lc;
            u32 off = r * 128 + 16 * (ch ^ (r & 7));
            LDSM_X4(bh[ng], sBh + off);
            LDSM_X4(bl[ng], sBl + off);
        }
        // pass 1: Ah*Bh  (16 independent accumulators)
#pragma unroll
        for (int mt = 0; mt < 4; mt++)
#pragma unroll
            for (int nt = 0; nt < 4; nt++) {
                const int ng = nt >> 1, hi = nt & 1;
                MMA_BF16(acc[mt][nt], ah[mt], bh[ng][hi], bh[ng][2 + hi]);
            }
        // pass 2: Ah*Bl
#pragma unroll
        for (int mt = 0; mt < 4; mt++)
#pragma unroll
            for (int nt = 0; nt < 4; nt++) {
                const int ng = nt >> 1, hi = nt & 1;
                MMA_BF16(acc[mt][nt], ah[mt], bl[ng][hi], bl[ng][2 + hi]);
            }
        // pass 3: Al*Bh
#pragma unroll
        for (int mt = 0; mt < 4; mt++)
#pragma unroll
            for (int nt = 0; nt < 4; nt++) {
                const int ng = nt >> 1, hi = nt & 1;
                MMA_BF16(acc[mt][nt], al[mt], bh[ng][hi], bh[ng][2 + hi]);
            }
    }
}

__device__ __forceinline__ void tgx_mainloop(
    u32 sb, const __nv_bfloat16* Abase_h, const __nv_bfloat16* Abase_l,
    const __nv_bfloat16* Bbase_h, const __nv_bfloat16* Bbase_l,
    int K, int tid, int wm, int wn, int lr16, int lc, float acc[4][4][4])
{
    const int NC = K >> 6;
    tgx_stage_load(sb, Abase_h, Abase_l, Bbase_h, Bbase_l, K, 0, tid);
    CP_COMMIT();
    if (NC > 1) {
        tgx_stage_load(sb + TGX_STAGE, Abase_h, Abase_l, Bbase_h, Bbase_l, K, 64, tid);
        CP_COMMIT();
    }
    for (int c = 0; c < NC; c++) {
        CP_WAIT(1);
        __syncthreads();
        if (c + 2 < NC) {
            tgx_stage_load(sb + ((c + 2) % 3) * TGX_STAGE,
                           Abase_h, Abase_l, Bbase_h, Bbase_l, K, (c + 2) * 64, tid);
            CP_COMMIT();
        } else {
            CP_COMMIT();
        }
        tgx_compute_chunk(sb + (c % 3) * TGX_STAGE, wm, wn, lr16, lc, acc);
    }
}

// Generic GEMM: MODE 0 fp32 out, MODE 1 relu+split
template <int MODE>
__global__ __launch_bounds__(256, 1)
void tgemm_kernel(const __nv_bfloat16* __restrict__ Ah,
                  const __nv_bfloat16* __restrict__ Al,
                  const __nv_bfloat16* __restrict__ Bh,
                  const __nv_bfloat16* __restrict__ Bl,
                  const float* __restrict__ bias,
                  float* __restrict__ Cf,
                  __nv_bfloat16* __restrict__ Ch,
                  __nv_bfloat16* __restrict__ Cl,
                  int M, int N, int K)
{
    extern __shared__ char smem[];
    const u32 sb = smem_u32(smem);
    const int tid  = threadIdx.x;
    const int wid  = tid >> 5, lane = tid & 31;
    const int wm   = wid >> 2, wn = wid & 3;
    const int m0   = blockIdx.y * 128;
    const int n0   = blockIdx.x * 128;
    const int lr16 = lane & 15, lc = lane >> 4;

    float acc[4][4][4];
#pragma unroll
    for (int mt = 0; mt < 4; mt++)
#pragma unroll
        for (int nt = 0; nt < 4; nt++)
#pragma unroll
            for (int r = 0; r < 4; r++) acc[mt][nt][r] = 0.0f;

    tgx_mainloop(sb, Ah + (size_t)m0 * K, Al + (size_t)m0 * K,
                 Bh + (size_t)n0 * K, Bl + (size_t)n0 * K,
                 K, tid, wm, wn, lr16, lc, acc);

    const int tg = lane >> 2;
    const int tc = (lane & 3) * 2;
#pragma unroll
    for (int mt = 0; mt < 4; mt++) {
#pragma unroll
        for (int half = 0; half < 2; half++) {
            const int m = m0 + wm * 64 + mt * 16 + tg + 8 * half;
#pragma unroll
            for (int nt = 0; nt < 4; nt++) {
                const int n = n0 + wn * 32 + nt * 8 + tc;
                float v0 = acc[mt][nt][2 * half]     + bias[n];
                float v1 = acc[mt][nt][2 * half + 1] + bias[n + 1];
                if (MODE == 0) {
                    *(float2*)(Cf + (size_t)m * N + n) = make_float2(v0, v1);
                } else {
                    v0 = fmaxf(v0, 0.0f); v1 = fmaxf(v1, 0.0f);
                    u32 hp, lp;
                    split2(v0, v1, hp, lp);
                    *(u32*)(Ch + (size_t)m * N + n) = hp;
                    *(u32*)(Cl + (size_t)m * N + n) = lp;
                }
            }
        }
    }
}

// Fused QKV: z=0 Q (scale 1/8, split out), z=1 K (split out),
// z=2 V (smem-staged transpose -> split V^T out directly).
__global__ __launch_bounds__(256, 1)
void qkv_fused_kernel(const __nv_bfloat16* __restrict__ xh,
                      const __nv_bfloat16* __restrict__ xl,
                      const __nv_bfloat16* __restrict__ wqh, const __nv_bfloat16* __restrict__ wql,
                      const __nv_bfloat16* __restrict__ wkh, const __nv_bfloat16* __restrict__ wkl,
                      const __nv_bfloat16* __restrict__ wvh, const __nv_bfloat16* __restrict__ wvl,
                      const float* __restrict__ bq, const float* __restrict__ bk,
                      const float* __restrict__ bv,
                      __nv_bfloat16* __restrict__ qh, __nv_bfloat16* __restrict__ ql,
                      __nv_bfloat16* __restrict__ kh, __nv_bfloat16* __restrict__ kl,
                      __nv_bfloat16* __restrict__ vth, __nv_bfloat16* __restrict__ vtl)
{
    extern __shared__ char smem[];
    const u32 sb = smem_u32(smem);
    const int tid  = threadIdx.x;
    const int wid  = tid >> 5, lane = tid & 31;
    const int wm   = wid >> 2, wn = wid & 3;
    const int m0   = blockIdx.y * 128;
    const int n0   = blockIdx.x * 128;
    const int z    = blockIdx.z;
    const int lr16 = lane & 15, lc = lane >> 4;

    const __nv_bfloat16* Bh = z == 0 ? wqh : z == 1 ? wkh : wvh;
    const __nv_bfloat16* Bl = z == 0 ? wql : z == 1 ? wkl : wvl;
    const float* bias       = z == 0 ? bq  : z == 1 ? bk  : bv;

    float acc[4][4][4];
#pragma unroll
    for (int mt = 0; mt < 4; mt++)
#pragma unroll
        for (int nt = 0; nt < 4; nt++)
#pragma unroll
            for (int r = 0; r < 4; r++) acc[mt][nt][r] = 0.0f;

    tgx_mainloop(sb, xh + (size_t)m0 * DD, xl + (size_t)m0 * DD,
                 Bh + (size_t)n0 * DD, Bl + (size_t)n0 * DD,
                 DD, tid, wm, wn, lr16, lc, acc);

    const int tg = lane >> 2;
    const int tc = (lane & 3) * 2;

    if (z != 2) {
        const float scl = (z == 0) ? 0.125f : 1.0f;
        __nv_bfloat16* Ch = z == 0 ? qh : kh;
        __nv_bfloat16* Cl = z == 0 ? ql : kl;
#pragma unroll
        for (int mt = 0; mt < 4; mt++) {
#pragma unroll
            for (int half = 0; half < 2; half++) {
                const int m = m0 + wm * 64 + mt * 16 + tg + 8 * half;
#pragma unroll
                for (int nt = 0; nt < 4; nt++) {
                    const int n = n0 + wn * 32 + nt * 8 + tc;
                    float v0 = (acc[mt][nt][2 * half]     + bias[n])     * scl;
                    float v1 = (acc[mt][nt][2 * half + 1] + bias[n + 1]) * scl;
                    u32 hp, lp;
                    split2(v0, v1, hp, lp);
                    *(u32*)(Ch + (size_t)m * DD + n) = hp;
                    *(u32*)(Cl + (size_t)m * DD + n) = lp;
                }
            }
        }
    } else {
        // V: stage fp32 tile in smem, write transposed split bf16 to Vt.
        float* tile = (float*)smem;     // [128][132]
        __syncthreads();                // mainloop LDSM consumers done
#pragma unroll
        for (int mt = 0; mt < 4; mt++) {
#pragma unroll
            for (int half = 0; half < 2; half++) {
                const int ml = wm * 64 + mt * 16 + tg + 8 * half;
#pragma unroll
                for (int nt = 0; nt < 4; nt++) {
                    const int nl = wn * 32 + nt * 8 + tc;
                    tile[ml * 132 + nl]     = acc[mt][nt][2 * half]     + bias[n0 + nl];
                    tile[ml * 132 + nl + 1] = acc[mt][nt][2 * half + 1] + bias[n0 + nl + 1];
                }
            }
        }
        __syncthreads();
        const int b    = m0 >> 11;
        const int tok0 = m0 & 2047;
        const int nl   = tid >> 1;
        const int mh   = (tid & 1) * 64;
        const size_t orow = (size_t)(b * 512 + n0 + nl) * LL + tok0 + mh;
#pragma unroll
        for (int it = 0; it < 8; it++) {
            u32 hp[4], lp[4];
#pragma unroll
            for (int j2 = 0; j2 < 4; j2++) {
                float v0 = tile[(mh + 8 * it + 2 * j2)     * 132 + nl];
                float v1 = tile[(mh + 8 * it + 2 * j2 + 1) * 132 + nl];
                split2(v0, v1, hp[j2], lp[j2]);
            }
            *(uint4*)(vth + orow + 8 * it) = *(uint4*)hp;
            *(uint4*)(vtl + orow + 8 * it) = *(uint4*)lp;
        }
    }
}

// ---------------------------------------------------------------------------
// HMMA flash attention with relative position bias (pass-major MMA order).
// ---------------------------------------------------------------------------
#define AT_STAGE 49152
#define AT_R3OFF (2 * AT_STAGE)
#define AT_RSTR  66
#define AT_SLOT  (128 * AT_RSTR)
#define AT_SMEM  (AT_R3OFF + 3 * AT_SLOT * 4)

__device__ __forceinline__ void attn_load_stage(
    u32 dstbase, int j0, int t, int tid, int b, int h,
    const __nv_bfloat16* __restrict__ kh, const __nv_bfloat16* __restrict__ kl,
    const __nv_bfloat16* __restrict__ relh, const __nv_bfloat16* __restrict__ rell,
    const __nv_bfloat16* __restrict__ vth, const __nv_bfloat16* __restrict__ vtl)
{
    const int r0 = tid >> 3, c = tid & 7;
#pragma unroll
    for (int i = 0; i < 2; i++) {
        const int r = r0 + 32 * i;
        const u32 sw = (u32)(r * 128 + 16 * (c ^ (r & 7)));
        const size_t krow = (size_t)(b * LL + j0 + r) * DD + h * DHH + 8 * c;
        const size_t frow = (size_t)(2047 - 64 * t - r) * DD + h * DHH + 8 * c;
        const size_t vrow = (size_t)((b * 8 + h) * 64 + r) * LL + j0 + 8 * c;
        cp16(dstbase +          sw, kh   + krow);
        cp16(dstbase +  8192 +  sw, kl   + krow);
        cp16(dstbase + 16384 +  sw, relh + frow);
        cp16(dstbase + 24576 +  sw, rell + frow);
        cp16(dstbase + 32768 +  sw, vth  + vrow);
        cp16(dstbase + 40960 +  sw, vtl  + vrow);
    }
}

__global__ __launch_bounds__(256, 1)
void attn_mma_kernel(const __nv_bfloat16* __restrict__ qh, const __nv_bfloat16* __restrict__ ql,
                     const __nv_bfloat16* __restrict__ kh, const __nv_bfloat16* __restrict__ kl,
                     const __nv_bfloat16* __restrict__ vth, const __nv_bfloat16* __restrict__ vtl,
                     const __nv_bfloat16* __restrict__ relh, const __nv_bfloat16* __restrict__ rell,
                     __nv_bfloat16* __restrict__ oh, __nv_bfloat16* __restrict__ ol)
{
    extern __shared__ char smem[];
    const u32 sb = smem_u32(smem);
    float* R3 = (float*)(smem + AT_R3OFF);

    const int tid = threadIdx.x, lane = tid & 31, w = tid >> 5;
    const int p   = blockIdx.x >> 4;
    const int bh  = blockIdx.x & 15;
    const int b   = bh >> 3, h = bh & 7;
    const int g   = lane >> 2, t4 = lane & 3;
    const int lr16 = lane & 15, lc = lane >> 4;

#pragma unroll 1
    for (int qq = 0; qq < 2; qq++) {
        const int q  = qq ? (15 - p) : p;
        const int i0 = q * 128;
        const int NT = 2 * q + 2;
        const int R0 = 16 * w + g, R1 = R0 + 8;
        const size_t rowg0 = (size_t)(b * LL + i0 + R0);

        u32 qfh[4][4], qfl[4][4];
        {
            const __nv_bfloat16* ph_ = qh + rowg0 * DD + h * DHH + 2 * t4;
            const __nv_bfloat16* pl_ = ql + rowg0 * DD + h * DHH + 2 * t4;
#pragma unroll
            for (int ks = 0; ks < 4; ks++) {
                qfh[ks][0] = *(const u32*)(ph_ + 16 * ks);
                qfh[ks][1] = *(const u32*)(ph_ + 16 * ks + 8 * DD);
                qfh[ks][2] = *(const u32*)(ph_ + 16 * ks + 8);
                qfh[ks][3] = *(const u32*)(ph_ + 16 * ks + 8 * DD + 8);
                qfl[ks][0] = *(const u32*)(pl_ + 16 * ks);
                qfl[ks][1] = *(const u32*)(pl_ + 16 * ks + 8 * DD);
                qfl[ks][2] = *(const u32*)(pl_ + 16 * ks + 8);
                qfl[ks][3] = *(const u32*)(pl_ + 16 * ks + 8 * DD + 8);
            }
        }

        float accO[8][4];
#pragma unroll
        for (int j = 0; j < 8; j++)
#pragma unroll
            for (int r = 0; r < 4; r++) accO[j][r] = 0.0f;
        float mrow0 = -1e30f, mrow1 = -1e30f, lrow0 = 0.0f, lrow1 = 0.0f;

        attn_load_stage(sb, i0 + 64, 0, tid, b, h, kh, kl, relh, rell, vth, vtl);
        CP_COMMIT();

#pragma unroll 1
        for (int t = 0; t < NT; t++) {
            const int j0 = i0 + 64 - 64 * t;
            if (t + 1 < NT) {
                attn_load_stage(sb + ((t + 1) & 1) * AT_STAGE, j0 - 64, t + 1,
                                tid, b, h, kh, kl, relh, rell, vth, vtl);
                CP_COMMIT();
                CP_WAIT(1);
            } else {
                CP_WAIT(0);
            }
            __syncthreads();

            const u32 st  = sb + (t & 1) * AT_STAGE;
            const u32 sKh = st, sKl = st + 8192, sFh = st + 16384,
                      sFl = st + 24576, sVh = st + 32768, sVl = st + 40960;

            // ---- R = Qs @ Fchunk^T (pass-major) ----
            {
                float racc[8][4];
#pragma unroll
                for (int j = 0; j < 8; j++)
#pragma unroll
                    for (int r = 0; r < 4; r++) racc[j][r] = 0.0f;
#pragma unroll
                for (int ks = 0; ks < 4; ks++) {
                    u32 fh[4][4], fl[4][4];
#pragma unroll
                    for (int ng = 0; ng < 4; ng++) {
                        const int row = 16 * ng + lr16;
                        const u32 off = (u32)(row * 128 + 16 * ((2 * ks + lc) ^ (row & 7)));
                        LDSM_X4(fh[ng], sFh + off);
                        LDSM_X4(fl[ng], sFl + off);
                    }
#pragma unroll
                    for (int ng = 0; ng < 4; ng++) {
                        MMA_BF16(racc[2*ng],   qfh[ks], fh[ng][0], fh[ng][2]);
                        MMA_BF16(racc[2*ng+1], qfh[ks], fh[ng][1], fh[ng][3]);
                    }
#pragma unroll
                    for (int ng = 0; ng < 4; ng++) {
                        MMA_BF16(racc[2*ng],   qfh[ks], fl[ng][0], fl[ng][2]);
                        MMA_BF16(racc[2*ng+1], qfh[ks], fl[ng][1], fl[ng][3]);
                    }
#pragma unroll
                    for (int ng = 0; ng < 4; ng++) {
                        MMA_BF16(racc[2*ng],   qfl[ks], fh[ng][0], fh[ng][2]);
                        MMA_BF16(racc[2*ng+1], qfl[ks], fh[ng][1], fh[ng][3]);
                    }
                }
                float* Rb = R3 + (t % 3) * AT_SLOT;
#pragma unroll
                for (int j = 0; j < 8; j++) {
                    *(float2*)&Rb[R0 * AT_RSTR + 8 * j + 2 * t4] = make_float2(racc[j][0], racc[j][1]);
                    *(float2*)&Rb[R1 * AT_RSTR + 8 * j + 2 * t4] = make_float2(racc[j][2], racc[j][3]);
                }
            }
            __syncwarp();

            // ---- S = Qs @ K^T (pass-major) ----
            float sacc[8][4];
#pragma unroll
            for (int j = 0; j < 8; j++)
#pragma unroll
                for (int r = 0; r < 4; r++) sacc[j][r] = 0.0f;
#pragma unroll
            for (int ks = 0; ks < 4; ks++) {
                u32 bkh_[4][4], bkl_[4][4];
#pragma unroll
                for (int ng = 0; ng < 4; ng++) {
                    const int row = 16 * ng + lr16;
                    const u32 off = (u32)(row * 128 + 16 * ((2 * ks + lc) ^ (row & 7)));
                    LDSM_X4(bkh_[ng], sKh + off);
                    LDSM_X4(bkl_[ng], sKl + off);
                }
#pragma unroll
                for (int ng = 0; ng < 4; ng++) {
                    MMA_BF16(sacc[2*ng],   qfh[ks], bkh_[ng][0], bkh_[ng][2]);
                    MMA_BF16(sacc[2*ng+1], qfh[ks], bkh_[ng][1], bkh_[ng][3]);
                }
#pragma unroll
                for (int ng = 0; ng < 4; ng++) {
                    MMA_BF16(sacc[2*ng],   qfh[ks], bkl_[ng][0], bkl_[ng][2]);
                    MMA_BF16(sacc[2*ng+1], qfh[ks], bkl_[ng][1], bkl_[ng][3]);
                }
#pragma unroll
                for (int ng = 0; ng < 4; ng++) {
                    MMA_BF16(sacc[2*ng],   qfl[ks], bkh_[ng][0], bkh_[ng][2]);
                    MMA_BF16(sacc[2*ng+1], qfl[ks], bkh_[ng][1], bkh_[ng][3]);
                }
            }

            // ---- gather skew bias + mask + online softmax ----
            float mx0 = -1e30f, mx1 = -1e30f;
#pragma unroll
            for (int j = 0; j < 8; j++) {
#pragma unroll
                for (int c2 = 0; c2 < 2; c2++) {
                    const int dj = 8 * j + 2 * t4 + c2;
                    {
                        const int e = 64 + R0 - dj;
                        const int slot = (t + 1 + (e >> 6)) % 3;
                        float sv = sacc[j][c2] + R3[slot * AT_SLOT + R0 * AT_RSTR + (e & 63)];
                        if (t < 2 && (64 * (t - 1) + R0 - dj) < 0) sv = -1e30f;
                        sacc[j][c2] = sv;
                        mx0 = fmaxf(mx0, sv);
                    }
                    {
                        const int e = 64 + R1 - dj;
                        const int slot = (t + 1 + (e >> 6)) % 3;
                        float sv = sacc[j][2 + c2] + R3[slot * AT_SLOT + R1 * AT_RSTR + (e & 63)];
                        if (t < 2 && (64 * (t - 1) + R1 - dj) < 0) sv = -1e30f;
                        sacc[j][2 + c2] = sv;
                        mx1 = fmaxf(mx1, sv);
                    }
                }
            }
            mx0 = fmaxf(mx0, __shfl_xor_sync(0xffffffffu, mx0, 1));
            mx0 = fmaxf(mx0, __shfl_xor_sync(0xffffffffu, mx0, 2));
            mx1 = fmaxf(mx1, __shfl_xor_sync(0xffffffffu, mx1, 1));
            mx1 = fmaxf(mx1, __shfl_xor_sync(0xffffffffu, mx1, 2));

            const float mn0 = fmaxf(mrow0, mx0), mn1 = fmaxf(mrow1, mx1);
            const float al0 = __expf(mrow0 - mn0), al1 = __expf(mrow1 - mn1);
            mrow0 = mn0; mrow1 = mn1;

            float rs0 = 0.0f, rs1 = 0.0f;
#pragma unroll
            for (int j = 0; j < 8; j++) {
#pragma unroll
                for (int c2 = 0; c2 < 2; c2++) {
                    float sv = sacc[j][c2];
                    float e  = __expf(sv - mn0);
                    if (sv < -1e29f) e = 0.0f;
                    rs0 += e; sacc[j][c2] = e;
                    sv = sacc[j][2 + c2];
                    e  = __expf(sv - mn1);
                    if (sv < -1e29f) e = 0.0f;
                    rs1 += e; sacc[j][2 + c2] = e;
                }
            }
            rs0 += __shfl_xor_sync(0xffffffffu, rs0, 1);
            rs0 += __shfl_xor_sync(0xffffffffu, rs0, 2);
            rs1 += __shfl_xor_sync(0xffffffffu, rs1, 1);
            rs1 += __shfl_xor_sync(0xffffffffu, rs1, 2);
            lrow0 = lrow0 * al0 + rs0;
            lrow1 = lrow1 * al1 + rs1;
#pragma unroll
            for (int j = 0; j < 8; j++) {
                accO[j][0] *= al0; accO[j][1] *= al0;
                accO[j][2] *= al1; accO[j][3] *= al1;
            }

            // ---- O += P @ V (pass-major) ----
#pragma unroll
            for (int ks = 0; ks < 4; ks++) {
                u32 ph_[4], pl_[4];
                split2(sacc[2*ks][0],   sacc[2*ks][1],   ph_[0], pl_[0]);
                split2(sacc[2*ks][2],   sacc[2*ks][3],   ph_[1], pl_[1]);
                split2(sacc[2*ks+1][0], sacc[2*ks+1][1], ph_[2], pl_[2]);
                split2(sacc[2*ks+1][2], sacc[2*ks+1][3], ph_[3], pl_[3]);
                u32 bvh_[4][4], bvl_[4][4];
#pragma unroll
                for (int ng = 0; ng < 4; ng++) {
                    const int row = 16 * ng + lr16;
                    const u32 off = (u32)(row * 128 + 16 * ((2 * ks + lc) ^ (row & 7)));
                    LDSM_X4(bvh_[ng], sVh + off);
                    LDSM_X4(bvl_[ng], sVl + off);
                }
#pragma unroll
                for (int ng = 0; ng < 4; ng++) {
                    MMA_BF16(accO[2*ng],   ph_, bvh_[ng][0], bvh_[ng][2]);
                    MMA_BF16(accO[2*ng+1], ph_, bvh_[ng][1], bvh_[ng][3]);
                }
#pragma unroll
                for (int ng = 0; ng < 4; ng++) {
                    MMA_BF16(accO[2*ng],   ph_, bvl_[ng][0], bvl_[ng][2]);
                    MMA_BF16(accO[2*ng+1], ph_, bvl_[ng][1], bvl_[ng][3]);
                }
#pragma unroll
                for (int ng = 0; ng < 4; ng++) {
                    MMA_BF16(accO[2*ng],   pl_, bvh_[ng][0], bvh_[ng][2]);
                    MMA_BF16(accO[2*ng+1], pl_, bvh_[ng][1], bvh_[ng][3]);
                }
            }
            __syncthreads();
        }

        const float inv0 = 1.0f / lrow0, inv1 = 1.0f / lrow1;
        __nv_bfloat16* o0h = oh + rowg0 * DD + h * DHH + 2 * t4;
        __nv_bfloat16* o0l = ol + rowg0 * DD + h * DHH + 2 * t4;
#pragma unroll
        for (int j = 0; j < 8; j++) {
            u32 hp, lp;
            split2(accO[j][0] * inv0, accO[j][1] * inv0, hp, lp);
            *(u32*)(o0h + 8 * j) = hp;
            *(u32*)(o0l + 8 * j) = lp;
            split2(accO[j][2] * inv1, accO[j][3] * inv1, hp, lp);
            *(u32*)(o0h + 8 * DD + 8 * j) = hp;
            *(u32*)(o0l + 8 * DD + 8 * j) = lp;
        }
    }
}

// ---------------------------------------------------------------------------
// Launch
// ---------------------------------------------------------------------------
extern "C" void kernel_launch(void* const* d_in, const int* in_sizes, int n_in,
                              void* d_out, int out_size)
{
    const float* x   = (const float*)d_in[0];
    // d_in[1] = mask — handled analytically
    const float* wq  = (const float*)d_in[2];
    const float* bq  = (const float*)d_in[3];
    const float* wk  = (const float*)d_in[4];
    const float* bk  = (const float*)d_in[5];
    const float* wv  = (const float*)d_in[6];
    const float* bv  = (const float*)d_in[7];
    const float* rel = (const float*)d_in[8];
    const float* w1  = (const float*)d_in[9];
    const float* b1  = (const float*)d_in[10];
    const float* w2  = (const float*)d_in[11];
    const float* b2  = (const float*)d_in[12];
    float* out = (float*)d_out;

    __nv_bfloat16 *xh, *xl, *qh, *ql, *kh, *kl, *vth, *vtl, *relh, *rell;
    __nv_bfloat16 *ah, *al, *hhp, *hlp;
    __nv_bfloat16 *wqh, *wql, *wkh, *wkl, *wvh, *wvl, *w1h, *w1l, *w2h, *w2l;
    cudaGetSymbolAddress((void**)&xh,  g_xh);   cudaGetSymbolAddress((void**)&xl,  g_xl);
    cudaGetSymbolAddress((void**)&qh,  g_qh);   cudaGetSymbolAddress((void**)&ql,  g_ql);
    cudaGetSymbolAddress((void**)&kh,  g_kh);   cudaGetSymbolAddress((void**)&kl,  g_kl);
    cudaGetSymbolAddress((void**)&vth, g_vth);  cudaGetSymbolAddress((void**)&vtl, g_vtl);
    cudaGetSymbolAddress((void**)&relh, g_relh); cudaGetSymbolAddress((void**)&rell, g_rell);
    cudaGetSymbolAddress((void**)&ah,  g_ah);   cudaGetSymbolAddress((void**)&al,  g_al);
    cudaGetSymbolAddress((void**)&hhp, g_hh);   cudaGetSymbolAddress((void**)&hlp, g_hl);
    cudaGetSymbolAddress((void**)&wqh, g_wqh);  cudaGetSymbolAddress((void**)&wql, g_wql);
    cudaGetSymbolAddress((void**)&wkh, g_wkh);  cudaGetSymbolAddress((void**)&wkl, g_wkl);
    cudaGetSymbolAddress((void**)&wvh, g_wvh);  cudaGetSymbolAddress((void**)&wvl, g_wvl);
    cudaGetSymbolAddress((void**)&w1h, g_w1h);  cudaGetSymbolAddress((void**)&w1l, g_w1l);
    cudaGetSymbolAddress((void**)&w2h, g_w2h);  cudaGetSymbolAddress((void**)&w2l, g_w2l);

    cudaFuncSetAttribute(tgemm_kernel<0>,  cudaFuncAttributeMaxDynamicSharedMemorySize, TGX_SMEM);
    cudaFuncSetAttribute(tgemm_kernel<1>,  cudaFuncAttributeMaxDynamicSharedMemorySize, TGX_SMEM);
    cudaFuncSetAttribute(qkv_fused_kernel, cudaFuncAttributeMaxDynamicSharedMemorySize, TGX_SMEM);
    cudaFuncSetAttribute(attn_mma_kernel,  cudaFuncAttributeMaxDynamicSharedMemorySize, AT_SMEM);

    // 0) Prep: split x+rel; transpose wq/wk/wv; transpose w1+w2 (fused)
    conv_xrel_kernel<<<(N4X + N4R + 255) / 256, 256>>>(
        (const float4*)x, (const float4*)rel, xh, xl, relh, rell);
    tsplit3_kernel<<<dim3(DD / 32, DD / 32, 3), 256>>>(
        wq, wk, wv, wqh, wql, wkh, wkl, wvh, wvl);
    tsplit_ffn_kernel<<<dim3(DFCN / 32, DD / 32, 2), 256>>>(
        w1, w2, w1h, w1l, w2h, w2l);

    // 1) Fused QKV (z=2 writes V^T split directly)
    qkv_fused_kernel<<<dim3(DD / 128, MM / 128, 3), 256, TGX_SMEM>>>(
        xh, xl, wqh, wql, wkh, wkl, wvh, wvl, bq, bk, bv, qh, ql, kh, kl, vth, vtl);

    // 2) HMMA flash attention with relative bias
    attn_mma_kernel<<<128, 256, AT_SMEM>>>(qh, ql, kh, kl, vth, vtl, relh, rell, ah, al);

    // 3) FFN
    tgemm_kernel<1><<<dim3(DFCN / 128, MM / 128), 256, TGX_SMEM>>>(
        ah, al, w1h, w1l, b1, nullptr, hhp, hlp, MM, DFCN, DD);
    tgemm_kernel<0><<<dim3(DD / 128, MM / 128), 256, TGX_SMEM>>>(
        hhp, hlp, w2h, w2l, b2, out, nullptr, nullptr, MM, DD, DFCN);
}